// round 3
// baseline (speedup 1.0000x reference)
#include <cuda_runtime.h>

// Problem constants
#define BATCH 32
#define SEQ   512
#define DIM   64
#define VOCAB 32000
#define DECAY 0.9f

// Scratch: gathered embeddings [B][S][D] fp32 = 4 MB (device global, no alloc)
__device__ float g_content[BATCH * SEQ * DIM];

// ---------------------------------------------------------------------------
// Kernel 1: embedding gather. content[b][s][d] = emb[x[b][s]][d]
// x is int32 (JAX x64 disabled downcasts the requested int64).
// Vectorized float4: B*S*D/4 = 262144 float4 elements, 16 per token.
// ---------------------------------------------------------------------------
__global__ void qmn_gather(const int* __restrict__ x,
                           const float* __restrict__ emb) {
    int idx = blockIdx.x * blockDim.x + threadIdx.x;  // float4 index
    const int n4 = BATCH * SEQ * DIM / 4;
    if (idx >= n4) return;
    int tok_idx = idx >> 4;      // 16 float4 per token (D=64)
    int d4      = idx & 15;
    int tok = x[tok_idx];
    // Defensive clamp: if dtype assumption is wrong we want rel_err, not a crash.
    if (tok < 0) tok = 0;
    if (tok >= VOCAB) tok = VOCAB - 1;
    const float4* src = reinterpret_cast<const float4*>(emb + (size_t)tok * DIM);
    reinterpret_cast<float4*>(g_content)[idx] = src[d4];
}

// ---------------------------------------------------------------------------
// Kernel 2: decayed outer-product scan.
//   rho_t[i][j] = DECAY * rho_{t-1}[i][j] + c_t[i]*c_t[j],  rho_{-1} = I
//   out[b][t][i][j] = rho_t[i][j]
//
// Grid: BATCH * CHUNKS blocks; each block owns 256 contiguous (i,j) entries
// of one batch row (4 rows of 64). 64 threads, 4 entries (float4) each.
// Double-buffered shared content row; prefetch next step into registers.
// ---------------------------------------------------------------------------
#define CHUNKS 16          // chunks per batch: D*D / 256
#define TPB    64

__global__ __launch_bounds__(TPB)
void qmn_scan(float* __restrict__ out) {
    __shared__ __align__(16) float sc[2][DIM];

    const int b     = blockIdx.x / CHUNKS;
    const int chunk = blockIdx.x % CHUNKS;
    const int tid   = threadIdx.x;

    const int e  = chunk * 256 + tid * 4;  // flattened (i,j) entry, j 4-aligned
    const int i  = e >> 6;                 // row 0..63
    const int jj = e & 63;                 // col base (multiple of 4)

    const float* __restrict__ cbase = g_content + (size_t)b * SEQ * DIM;

    // Preload t=0 content row (all 64 threads load one float each)
    sc[0][tid] = cbase[tid];

    // rho_{-1} = Identity
    float4 rho;
    rho.x = (i == jj + 0) ? 1.0f : 0.0f;
    rho.y = (i == jj + 1) ? 1.0f : 0.0f;
    rho.z = (i == jj + 2) ? 1.0f : 0.0f;
    rho.w = (i == jj + 3) ? 1.0f : 0.0f;

    // Output base: out[b][t][i][j]; step t advances by D*D floats = 1024 float4
    float4* __restrict__ outp =
        reinterpret_cast<float4*>(out + (size_t)b * SEQ * DIM * DIM) + (e >> 2);

    __syncthreads();

    #pragma unroll 4
    for (int t = 0; t < SEQ; t++) {
        // Prefetch next step's content element into a register (hides L2 latency)
        float nxt = 0.0f;
        if (t + 1 < SEQ) nxt = cbase[(t + 1) * DIM + tid];

        const int cur = t & 1;
        const float  ci  = sc[cur][i];
        const float4 cj4 = *reinterpret_cast<const float4*>(&sc[cur][jj]);

        rho.x = fmaf(rho.x, DECAY, ci * cj4.x);
        rho.y = fmaf(rho.y, DECAY, ci * cj4.y);
        rho.z = fmaf(rho.z, DECAY, ci * cj4.z);
        rho.w = fmaf(rho.w, DECAY, ci * cj4.w);

        outp[(size_t)t * (DIM * DIM / 4)] = rho;

        if (t + 1 < SEQ) sc[cur ^ 1][tid] = nxt;
        __syncthreads();
    }
}

// ---------------------------------------------------------------------------
// Launch
// ---------------------------------------------------------------------------
extern "C" void kernel_launch(void* const* d_in, const int* in_sizes, int n_in,
                              void* d_out, int out_size) {
    const int*   x   = (const int*)d_in[0];     // [B, S] int32 (int64 downcast)
    const float* emb = (const float*)d_in[1];   // [VOCAB, D] fp32
    float*       out = (float*)d_out;           // [B, S, D, D] fp32

    (void)in_sizes; (void)n_in; (void)out_size;

    // Gather: 262144 float4 elements
    {
        const int n4 = BATCH * SEQ * DIM / 4;
        const int tpb = 256;
        qmn_gather<<<(n4 + tpb - 1) / tpb, tpb>>>(x, emb);
    }

    // Scan: 32 batches x 16 chunks = 512 blocks of 64 threads
    qmn_scan<<<BATCH * CHUNKS, TPB>>>(out);
}

// round 4
// speedup vs baseline: 3.3846x; 3.3846x over previous
#include <cuda_runtime.h>

// Problem constants
#define BATCH 32
#define SEQ   512
#define DIM   64
#define VOCAB 32000
#define DECAY 0.9f

#define T_CHUNK 16
#define NCHUNK  32                       // SEQ / T_CHUNK
#define D_CHUNK 0.1853020188851841f     // 0.9^16

// Device-global scratch (no runtime allocation)
__device__ float g_content[BATCH * SEQ * DIM];                 // 4 MB
__device__ float g_L[BATCH * NCHUNK * DIM * DIM];              // 16 MB
__device__ float g_cin[BATCH * NCHUNK * DIM * DIM];            // 16 MB

// ---------------------------------------------------------------------------
// Kernel 1: embedding gather. content[b][s][d] = emb[x[b][s]][d]  (x is int32)
// ---------------------------------------------------------------------------
__global__ void qmn_gather(const int* __restrict__ x,
                           const float* __restrict__ emb) {
    int idx = blockIdx.x * blockDim.x + threadIdx.x;  // float4 index
    const int n4 = BATCH * SEQ * DIM / 4;
    if (idx >= n4) return;
    int tok_idx = idx >> 4;      // 16 float4 per token (D=64)
    int d4      = idx & 15;
    int tok = x[tok_idx];
    if (tok < 0) tok = 0;
    if (tok >= VOCAB) tok = VOCAB - 1;
    const float4* src = reinterpret_cast<const float4*>(emb + (size_t)tok * DIM);
    reinterpret_cast<float4*>(g_content)[idx] = src[d4];
}

// ---------------------------------------------------------------------------
// Kernel 2 (B1): per-chunk local decayed sums.
//   L_k[i][j] = sum_{t=0..T-1} DECAY^{T-1-t} * c_{k*T+t}[i] * c_{k*T+t}[j]
// Block = (b, k); 256 threads; thread owns 4 float4: q = tid + f*256
//   -> i = (tid>>4) + f*16, j = (tid&15)*4 .. +3
// ---------------------------------------------------------------------------
__global__ __launch_bounds__(256)
void qmn_chunk_sum() {
    __shared__ __align__(16) float sc[T_CHUNK * DIM];   // 4 KB

    const int b   = blockIdx.x / NCHUNK;
    const int k   = blockIdx.x % NCHUNK;
    const int tid = threadIdx.x;

    const float* __restrict__ cbase =
        g_content + ((size_t)b * SEQ + k * T_CHUNK) * DIM;

    // Load chunk content: 1024 floats = 256 float4, one per thread
    reinterpret_cast<float4*>(sc)[tid] =
        reinterpret_cast<const float4*>(cbase)[tid];
    __syncthreads();

    const int jj = (tid & 15) * 4;
    const int i0 = tid >> 4;

    float4 acc[4];
    #pragma unroll
    for (int f = 0; f < 4; f++) acc[f] = make_float4(0.f, 0.f, 0.f, 0.f);

    #pragma unroll
    for (int t = 0; t < T_CHUNK; t++) {
        const float* row = sc + t * DIM;
        const float4 cj = *reinterpret_cast<const float4*>(row + jj);
        #pragma unroll
        for (int f = 0; f < 4; f++) {
            const float ci = row[i0 + f * 16];
            acc[f].x = fmaf(acc[f].x, DECAY, ci * cj.x);
            acc[f].y = fmaf(acc[f].y, DECAY, ci * cj.y);
            acc[f].z = fmaf(acc[f].z, DECAY, ci * cj.z);
            acc[f].w = fmaf(acc[f].w, DECAY, ci * cj.w);
        }
    }

    float4* __restrict__ Lp = reinterpret_cast<float4*>(
        g_L + ((size_t)b * NCHUNK + k) * DIM * DIM);
    #pragma unroll
    for (int f = 0; f < 4; f++) Lp[tid + f * 256] = acc[f];
}

// ---------------------------------------------------------------------------
// Kernel 3 (B2): sequential carry combine over chunks (32 steps, tiny).
//   Cin_0 = I ;  R_k = D_CHUNK * R_{k-1} + L_k ;  Cin_{k+1} = R_k
// 32768 float4 lanes total.
// ---------------------------------------------------------------------------
__global__ __launch_bounds__(256)
void qmn_carry() {
    const int idx = blockIdx.x * 256 + threadIdx.x;  // [0, 32768)
    const int b = idx >> 10;
    const int q = idx & 1023;
    const int i  = q >> 4;
    const int j0 = (q & 15) * 4;

    float4 R;
    R.x = (i == j0 + 0) ? 1.0f : 0.0f;
    R.y = (i == j0 + 1) ? 1.0f : 0.0f;
    R.z = (i == j0 + 2) ? 1.0f : 0.0f;
    R.w = (i == j0 + 3) ? 1.0f : 0.0f;

    const float4* __restrict__ Lp = reinterpret_cast<const float4*>(g_L);
    float4* __restrict__ Cp       = reinterpret_cast<float4*>(g_cin);

    #pragma unroll
    for (int k = 0; k < NCHUNK; k++) {
        const size_t o = ((size_t)b * NCHUNK + k) * 1024 + q;
        Cp[o] = R;
        const float4 l = Lp[o];
        R.x = fmaf(R.x, D_CHUNK, l.x);
        R.y = fmaf(R.y, D_CHUNK, l.y);
        R.z = fmaf(R.z, D_CHUNK, l.z);
        R.w = fmaf(R.w, D_CHUNK, l.w);
    }
}

// ---------------------------------------------------------------------------
// Kernel 4 (C): emit all states. Block = (b, k), carry-in from g_cin.
// No barriers inside the time loop; streaming stores.
// ---------------------------------------------------------------------------
__global__ __launch_bounds__(256)
void qmn_states(float* __restrict__ out) {
    __shared__ __align__(16) float sc[T_CHUNK * DIM];   // 4 KB

    const int b   = blockIdx.x / NCHUNK;
    const int k   = blockIdx.x % NCHUNK;
    const int tid = threadIdx.x;

    const float* __restrict__ cbase =
        g_content + ((size_t)b * SEQ + k * T_CHUNK) * DIM;
    reinterpret_cast<float4*>(sc)[tid] =
        reinterpret_cast<const float4*>(cbase)[tid];

    const int jj = (tid & 15) * 4;
    const int i0 = tid >> 4;

    // Carry-in (state before first step of this chunk)
    const float4* __restrict__ Cp = reinterpret_cast<const float4*>(
        g_cin + ((size_t)b * NCHUNK + k) * DIM * DIM);
    float4 acc[4];
    #pragma unroll
    for (int f = 0; f < 4; f++) acc[f] = Cp[tid + f * 256];

    float4* __restrict__ op = reinterpret_cast<float4*>(
        out + ((size_t)b * SEQ + k * T_CHUNK) * DIM * DIM);

    __syncthreads();

    #pragma unroll 4
    for (int t = 0; t < T_CHUNK; t++) {
        const float* row = sc + t * DIM;
        const float4 cj = *reinterpret_cast<const float4*>(row + jj);
        #pragma unroll
        for (int f = 0; f < 4; f++) {
            const float ci = row[i0 + f * 16];
            acc[f].x = fmaf(acc[f].x, DECAY, ci * cj.x);
            acc[f].y = fmaf(acc[f].y, DECAY, ci * cj.y);
            acc[f].z = fmaf(acc[f].z, DECAY, ci * cj.z);
            acc[f].w = fmaf(acc[f].w, DECAY, ci * cj.w);
        }
        #pragma unroll
        for (int f = 0; f < 4; f++)
            __stcs(&op[(size_t)t * 1024 + tid + f * 256], acc[f]);
    }
}

// ---------------------------------------------------------------------------
// Launch
// ---------------------------------------------------------------------------
extern "C" void kernel_launch(void* const* d_in, const int* in_sizes, int n_in,
                              void* d_out, int out_size) {
    const int*   x   = (const int*)d_in[0];     // [B, S] int32
    const float* emb = (const float*)d_in[1];   // [VOCAB, D] fp32
    float*       out = (float*)d_out;           // [B, S, D, D] fp32

    (void)in_sizes; (void)n_in; (void)out_size;

    {   // Gather: 262144 float4 elements
        const int n4 = BATCH * SEQ * DIM / 4;
        qmn_gather<<<(n4 + 255) / 256, 256>>>(x, emb);
    }
    // B1: per-chunk local sums: 32*32 = 1024 blocks
    qmn_chunk_sum<<<BATCH * NCHUNK, 256>>>();
    // B2: carry combine: 32768 float4 lanes / 256
    qmn_carry<<<128, 256>>>();
    // C: state emission: 1024 blocks
    qmn_states<<<BATCH * NCHUNK, 256>>>(out);
}

// round 5
// speedup vs baseline: 4.2403x; 1.2528x over previous
#include <cuda_runtime.h>

// Problem constants
#define BATCH 32
#define SEQ   512
#define DIM   64
#define VOCAB 32000
#define DECAY 0.9f

#define T_CHUNK 16
#define NCHUNK  32                      // SEQ / T_CHUNK
#define DC      0.1853020188851841f     // 0.9^16 (chunk decay)
#define MTERMS  10                      // carry terms kept; err ~0.9^160 = 4.8e-8

// Scratch: per-chunk local sums L_k [B][NCHUNK][D][D] = 16 MB (L2-resident)
__device__ float g_L[BATCH * NCHUNK * DIM * DIM];

// Gather one chunk's 16 token embeddings into smem: sc[s][d], 256 thr, 1 float4 each
__device__ __forceinline__ void gather_chunk(const int* __restrict__ x,
                                             const float* __restrict__ emb,
                                             float* sc, int b, int k, int tid) {
    const int s  = tid >> 4;     // token within chunk
    const int d4 = tid & 15;     // float4 within row
    int tok = x[b * SEQ + k * T_CHUNK + s];
    tok = min(max(tok, 0), VOCAB - 1);
    reinterpret_cast<float4*>(sc)[tid] =
        reinterpret_cast<const float4*>(emb + (size_t)tok * DIM)[d4];
}

// ---------------------------------------------------------------------------
// Kernel B1: gather + per-chunk local decayed sums.
//   L_k[i][j] = sum_{t} DECAY^{T-1-t} * c_t[i] * c_t[j]
// Thread owns a 4x4 tile: rows i0..i0+3, cols j0..j0+3.
// ---------------------------------------------------------------------------
__global__ __launch_bounds__(256)
void qmn_chunk_sum(const int* __restrict__ x, const float* __restrict__ emb) {
    __shared__ __align__(16) float sc[T_CHUNK * DIM];   // 4 KB

    const int b   = blockIdx.x / NCHUNK;
    const int k   = blockIdx.x % NCHUNK;
    const int tid = threadIdx.x;

    gather_chunk(x, emb, sc, b, k, tid);
    __syncthreads();

    const int i0 = (tid >> 4) * 4;
    const int j0 = (tid & 15) * 4;

    float4 acc[4];
    #pragma unroll
    for (int r = 0; r < 4; r++) acc[r] = make_float4(0.f, 0.f, 0.f, 0.f);

    #pragma unroll
    for (int t = 0; t < T_CHUNK; t++) {
        const float4 ci = *reinterpret_cast<const float4*>(sc + t * DIM + i0);
        const float4 cj = *reinterpret_cast<const float4*>(sc + t * DIM + j0);
        const float c[4] = {ci.x, ci.y, ci.z, ci.w};
        #pragma unroll
        for (int r = 0; r < 4; r++) {
            acc[r].x = fmaf(acc[r].x, DECAY, c[r] * cj.x);
            acc[r].y = fmaf(acc[r].y, DECAY, c[r] * cj.y);
            acc[r].z = fmaf(acc[r].z, DECAY, c[r] * cj.z);
            acc[r].w = fmaf(acc[r].w, DECAY, c[r] * cj.w);
        }
    }

    float* Lp = g_L + (size_t)blockIdx.x * DIM * DIM;   // blockIdx.x == b*NCHUNK+k
    #pragma unroll
    for (int r = 0; r < 4; r++)
        *reinterpret_cast<float4*>(Lp + (i0 + r) * DIM + j0) = acc[r];
}

// ---------------------------------------------------------------------------
// Kernel C: state emission. Carry-in recomputed from the last MTERMS L's
// (geometric truncation, error ~0.9^160), then 16 barrier-free emit steps.
// ---------------------------------------------------------------------------
__global__ __launch_bounds__(256)
void qmn_states(const int* __restrict__ x, const float* __restrict__ emb,
                float* __restrict__ out) {
    __shared__ __align__(16) float sc[T_CHUNK * DIM];   // 4 KB

    const int b   = blockIdx.x / NCHUNK;
    const int k   = blockIdx.x % NCHUNK;
    const int tid = threadIdx.x;

    gather_chunk(x, emb, sc, b, k, tid);

    const int i0 = (tid >> 4) * 4;
    const int j0 = (tid & 15) * 4;

    // Carry-in: acc = sum_{m=k-1 down} DC^{k-1-m} * L_m  (+ DC^k * I for small k)
    float4 acc[4];
    #pragma unroll
    for (int r = 0; r < 4; r++) acc[r] = make_float4(0.f, 0.f, 0.f, 0.f);

    const float* Lb = g_L + (size_t)b * NCHUNK * DIM * DIM;
    const int mlo = (k - MTERMS > 0) ? (k - MTERMS) : 0;
    float w = 1.0f;                       // DC^{k-1-m}, m descending
    for (int m = k - 1; m >= mlo; m--) {
        const float* Lp = Lb + (size_t)m * DIM * DIM;
        #pragma unroll
        for (int r = 0; r < 4; r++) {
            const float4 l = *reinterpret_cast<const float4*>(Lp + (i0 + r) * DIM + j0);
            acc[r].x = fmaf(w, l.x, acc[r].x);
            acc[r].y = fmaf(w, l.y, acc[r].y);
            acc[r].z = fmaf(w, l.z, acc[r].z);
            acc[r].w = fmaf(w, l.w, acc[r].w);
        }
        w *= DC;
    }
    if (k <= MTERMS) {
        // Loop ran exactly k times -> w == DC^k. Add identity term on diagonal.
        #pragma unroll
        for (int r = 0; r < 4; r++) {
            const int i = i0 + r;
            if (i == j0 + 0) acc[r].x += w;
            if (i == j0 + 1) acc[r].y += w;
            if (i == j0 + 2) acc[r].z += w;
            if (i == j0 + 3) acc[r].w += w;
        }
    }

    float* op = out + ((size_t)b * SEQ + (size_t)k * T_CHUNK) * DIM * DIM;

    __syncthreads();

    #pragma unroll
    for (int t = 0; t < T_CHUNK; t++) {
        const float4 ci = *reinterpret_cast<const float4*>(sc + t * DIM + i0);
        const float4 cj = *reinterpret_cast<const float4*>(sc + t * DIM + j0);
        const float c[4] = {ci.x, ci.y, ci.z, ci.w};
        #pragma unroll
        for (int r = 0; r < 4; r++) {
            acc[r].x = fmaf(acc[r].x, DECAY, c[r] * cj.x);
            acc[r].y = fmaf(acc[r].y, DECAY, c[r] * cj.y);
            acc[r].z = fmaf(acc[r].z, DECAY, c[r] * cj.z);
            acc[r].w = fmaf(acc[r].w, DECAY, c[r] * cj.w);
        }
        float* ot = op + (size_t)t * DIM * DIM;
        #pragma unroll
        for (int r = 0; r < 4; r++)
            __stcs(reinterpret_cast<float4*>(ot + (i0 + r) * DIM + j0), acc[r]);
    }
}

// ---------------------------------------------------------------------------
// Launch
// ---------------------------------------------------------------------------
extern "C" void kernel_launch(void* const* d_in, const int* in_sizes, int n_in,
                              void* d_out, int out_size) {
    const int*   x   = (const int*)d_in[0];     // [B, S] int32
    const float* emb = (const float*)d_in[1];   // [VOCAB, D] fp32
    float*       out = (float*)d_out;           // [B, S, D, D] fp32

    (void)in_sizes; (void)n_in; (void)out_size;

    qmn_chunk_sum<<<BATCH * NCHUNK, 256>>>(x, emb);
    qmn_states<<<BATCH * NCHUNK, 256>>>(x, emb, out);
}